// round 9
// baseline (speedup 1.0000x reference)
#include <cuda_runtime.h>

#define OH   113        // output windows per dim
#define P    24         // smem row pitch (in float2 elements)
#define NT   512        // threads per CTA

// Tile: 8x8 windows. Pyramid kept only to L1:
//   L0: 23x23   L1: 22x22
// All coarser scales (16/32/64px) derive from the SAME 64 L1 taps per window.
#define R0   0
#define R1   (23*P)              // 552
#define RT   (R1 + 22*P)         // 1080 float2 = 8.6KB

__global__ __launch_bounds__(NT)
void k_fused(const float* __restrict__ img, float* __restrict__ out) {
    __shared__ float2 s[RT];        // (max, min): L0 then L1
    __shared__ float  c0[23 * 9];   // L0 column range-sums (16 taps), pitch 9

    const int tid = threadIdx.x;
    const int I0 = blockIdx.y * 8;      // tile origin, stride-4 grid units
    const int J0 = blockIdx.x * 8;

    // ---- Phase A: level-0 4x4 max/min over 23x23 local origins ----
    // Branchless clamp: clamped entries only feed discarded windows.
    const float4* p4 = (const float4*)img;
    for (int e = tid; e < 23 * 23; e += NT) {
        int i = e / 23, j = e - i * 23;
        int gi = min(I0 + i, 127), gj = min(J0 + j, 127);
        float mx = -3.4e38f, mn = 3.4e38f;
#pragma unroll
        for (int k = 0; k < 4; k++) {
            float4 v = p4[(4 * gi + k) * 128 + gj];
            mx = fmaxf(mx, fmaxf(fmaxf(v.x, v.y), fmaxf(v.z, v.w)));
            mn = fminf(mn, fminf(fminf(v.x, v.y), fminf(v.z, v.w)));
        }
        s[R0 + i * P + j] = make_float2(mx, mn);
    }
    __syncthreads();

    // ---- Phase B: L1 (22x22, 4 taps) and c0 (23x8, 16 taps) from L0 ----
    for (int e = tid; e < 22 * 22 + 23 * 8; e += NT) {
        if (e < 22 * 22) {
            int i = e / 22, j = e - i * 22;
            int b = R0 + i * P + j;
            float2 a0 = s[b],     a1 = s[b + 1];
            float2 a2 = s[b + P], a3 = s[b + P + 1];
            s[R1 + i * P + j] = make_float2(
                fmaxf(fmaxf(a0.x, a1.x), fmaxf(a2.x, a3.x)),
                fminf(fminf(a0.y, a1.y), fminf(a2.y, a3.y)));
        } else {
            int f = e - 22 * 22;
            int i = f >> 3, J = f & 7;
            float sum = 0.f;
#pragma unroll
            for (int q = 0; q < 16; q++) {
                float2 v = s[R0 + i * P + J + q];
                sum += v.x - v.y;
            }
            c0[i * 9 + J] = sum;
        }
    }
    __syncthreads();

    // ---- Phase E: 8 threads/window; thread h owns tap row a=h ----
    // Tap grid T[a][b] = L1(ti+2a, tj+2b), a,b in 0..7. All of s1..s4 derive
    // from it:  s1 = sum ranges of all taps; s2 boxes = 2x2 tap groups;
    // s3 boxes = 4x4 tap groups; s4 = global tap max/min.
    const unsigned FM = 0xFFFFFFFFu;
    int w  = tid >> 3;          // window 0..63
    int h  = tid & 7;
    int ti = w >> 3, tj = w & 7;

    float2 T[8];
    {
        int base = R1 + (ti + 2 * h) * P + tj;
#pragma unroll
        for (int b = 0; b < 8; b++) T[b] = s[base + 2 * b];
    }

    // Per-thread (row-local) partials
    float s1p = 0.f, m4 = -3.4e38f, n4 = 3.4e38f;
    float m2[4], n2[4], m3[2], n3[2];
#pragma unroll
    for (int b = 0; b < 8; b++) {
        s1p += T[b].x - T[b].y;
        m4 = fmaxf(m4, T[b].x);
        n4 = fminf(n4, T[b].y);
    }
#pragma unroll
    for (int q = 0; q < 4; q++) {
        m2[q] = fmaxf(T[2 * q].x, T[2 * q + 1].x);
        n2[q] = fminf(T[2 * q].y, T[2 * q + 1].y);
    }
#pragma unroll
    for (int c = 0; c < 2; c++) {
        m3[c] = fmaxf(fmaxf(T[4 * c].x, T[4 * c + 1].x),
                      fmaxf(T[4 * c + 2].x, T[4 * c + 3].x));
        n3[c] = fminf(fminf(T[4 * c].y, T[4 * c + 1].y),
                      fminf(T[4 * c + 2].y, T[4 * c + 3].y));
    }
    // s0 partial: c0 rows 2h, 2h+1
    float s0p = c0[(ti + 2 * h) * 9 + tj] + c0[(ti + 2 * h + 1) * 9 + tj];

    // --- cross-thread reductions (8-lane groups, within warp) ---
    // s2: pair rows (a=2p, 2p+1)
#pragma unroll
    for (int q = 0; q < 4; q++) {
        m2[q] = fmaxf(m2[q], __shfl_xor_sync(FM, m2[q], 1));
        n2[q] = fminf(n2[q], __shfl_xor_sync(FM, n2[q], 1));
    }
    float s2 = (m2[0] - n2[0]) + (m2[1] - n2[1])
             + (m2[2] - n2[2]) + (m2[3] - n2[3]);
    s2 += __shfl_xor_sync(FM, s2, 2);
    s2 += __shfl_xor_sync(FM, s2, 4);

    // s3: quad rows (a = 4bp..4bp+3)
#pragma unroll
    for (int c = 0; c < 2; c++) {
        m3[c] = fmaxf(m3[c], __shfl_xor_sync(FM, m3[c], 1));
        n3[c] = fminf(n3[c], __shfl_xor_sync(FM, n3[c], 1));
        m3[c] = fmaxf(m3[c], __shfl_xor_sync(FM, m3[c], 2));
        n3[c] = fminf(n3[c], __shfl_xor_sync(FM, n3[c], 2));
    }
    float s3 = (m3[0] - n3[0]) + (m3[1] - n3[1]);
    s3 += __shfl_xor_sync(FM, s3, 4);

    // s0, s1, s4: full 8-lane trees
#pragma unroll
    for (int off = 1; off <= 4; off <<= 1) {
        s0p += __shfl_xor_sync(FM, s0p, off);
        s1p += __shfl_xor_sync(FM, s1p, off);
        m4 = fmaxf(m4, __shfl_xor_sync(FM, m4, off));
        n4 = fminf(n4, __shfl_xor_sync(FM, n4, off));
    }

    int I = I0 + ti, J = J0 + tj;
    if (h == 0 && I < OH && J < OH) {
        float s4 = m4 - n4;
        float num = 2.0f * __log2f(s0p) + 3.0f * __log2f(s1p)
                  + 4.0f * __log2f(s2) + 5.0f * __log2f(s3)
                  + 6.0f * __log2f(s4);
        out[I * OH + J] = -num * (1.0f / 90.0f);
    }
}

// ---------------------------------------------------------------------------
extern "C" void kernel_launch(void* const* d_in, const int* in_sizes, int n_in,
                              void* d_out, int out_size) {
    const float* img = (const float*)d_in[0];
    float* out = (float*)d_out;
    dim3 grid(15, 15);          // ceil(113/8) per dim = 225 CTAs
    k_fused<<<grid, NT>>>(img, out);
}

// round 13
// speedup vs baseline: 1.3301x; 1.3301x over previous
#include <cuda_runtime.h>

#define OH   113        // output windows per dim
#define P    24         // smem row pitch (in float2 elements)

// Tile: 8x8 windows. Local pyramid extents (rows x cols):
//   L0: 23x23  L1: 22x22  L2: 20x20   (L3/L4 folded into epilogue)
// Pyramid entry: float2 { .x = max, .y = min }
#define R0   0
#define R1   (23*P)              // 552
#define R2   (R1 + 22*P)         // 1080
#define RT   (R2 + 20*P)         // 1560 float2 = 12.2KB

__device__ __forceinline__ float vmax4(float4 v) {
    return fmaxf(fmaxf(v.x, v.y), fmaxf(v.z, v.w));
}
__device__ __forceinline__ float vmin4(float4 v) {
    return fminf(fminf(v.x, v.y), fminf(v.z, v.w));
}

__global__ __launch_bounds__(256)
void k_fused(const float* __restrict__ img, float* __restrict__ out) {
    __shared__ float2 s[RT];        // (max, min) pyramid
    __shared__ float  c0[23 * 9];   // L0 column range-sums (16 taps), pitch 9
    __shared__ float  c1[22 * 9];   // L1 column range-sums (8 taps, stride 2)

    const int tid = threadIdx.x;
    const int I0 = blockIdx.y * 8;      // tile origin, stride-4 grid units
    const int J0 = blockIdx.x * 8;

    // ---- Phase A: level-0 4x4 max/min over 23x23 local origins ----
    // 529 elements, 256 threads: element tid and tid+256; ALL 8 LDG.128
    // issued before any combine (MLP=8). Branchless clamp: clamped entries
    // only ever feed discarded windows.
    const float4* p4 = (const float4*)img;
    {
        int i0 = tid / 23, j0 = tid - i0 * 23;
        int gi0 = min(I0 + i0, 127), gj0 = min(J0 + j0, 127);
        const float4* r0p = p4 + 4 * gi0 * 128 + gj0;

        int e1 = tid + 256;
        int has1 = e1 < 23 * 23;
        int i1 = e1 / 23, j1 = e1 - i1 * 23;
        int gi1 = min(I0 + i1, 127), gj1 = min(J0 + j1, 127);
        const float4* r1p = has1 ? (p4 + 4 * gi1 * 128 + gj1) : r0p;

        float4 a0 = r0p[0], a1 = r0p[128], a2 = r0p[256], a3 = r0p[384];
        float4 b0 = r1p[0], b1 = r1p[128], b2 = r1p[256], b3 = r1p[384];

        float mxa = fmaxf(fmaxf(vmax4(a0), vmax4(a1)),
                          fmaxf(vmax4(a2), vmax4(a3)));
        float mna = fminf(fminf(vmin4(a0), vmin4(a1)),
                          fminf(vmin4(a2), vmin4(a3)));
        s[R0 + i0 * P + j0] = make_float2(mxa, mna);

        if (has1) {
            float mxb = fmaxf(fmaxf(vmax4(b0), vmax4(b1)),
                              fmaxf(vmax4(b2), vmax4(b3)));
            float mnb = fminf(fminf(vmin4(b0), vmin4(b1)),
                              fminf(vmin4(b2), vmin4(b3)));
            s[R0 + i1 * P + j1] = make_float2(mxb, mnb);
        }
    }
    __syncthreads();

    // ---- Phase B: L1 (22x22, 4 taps) and c0 (23x8, 16 taps) from L0 ----
    for (int e = tid; e < 22 * 22 + 23 * 8; e += 256) {
        if (e < 22 * 22) {
            int i = e / 22, j = e - i * 22;
            int b = R0 + i * P + j;
            float2 a0 = s[b],     a1 = s[b + 1];
            float2 a2 = s[b + P], a3 = s[b + P + 1];
            s[R1 + i * P + j] = make_float2(
                fmaxf(fmaxf(a0.x, a1.x), fmaxf(a2.x, a3.x)),
                fminf(fminf(a0.y, a1.y), fminf(a2.y, a3.y)));
        } else {
            int f = e - 22 * 22;
            int i = f >> 3, J = f & 7;
            float sum = 0.f;
#pragma unroll
            for (int q = 0; q < 16; q++) {
                float2 v = s[R0 + i * P + J + q];
                sum += v.x - v.y;
            }
            c0[i * 9 + J] = sum;
        }
    }
    __syncthreads();

    // ---- Phase C: L2 (20x20, 4 taps d=2) and c1 (22x8, 8 taps stride 2) ----
    for (int e = tid; e < 20 * 20 + 22 * 8; e += 256) {
        if (e < 20 * 20) {
            int i = e / 20, j = e - i * 20;
            int b = R1 + i * P + j;
            float2 a0 = s[b],         a1 = s[b + 2];
            float2 a2 = s[b + 2 * P], a3 = s[b + 2 * P + 2];
            s[R2 + i * P + j] = make_float2(
                fmaxf(fmaxf(a0.x, a1.x), fmaxf(a2.x, a3.x)),
                fminf(fminf(a0.y, a1.y), fminf(a2.y, a3.y)));
        } else {
            int f = e - 20 * 20;
            int i = f >> 3, J = f & 7;
            float sum = 0.f;
#pragma unroll
            for (int q = 0; q < 8; q++) {
                float2 v = s[R1 + i * P + J + 2 * q];
                sum += v.x - v.y;
            }
            c1[i * 9 + J] = sum;
        }
    }
    __syncthreads();

    // ---- Phase E: 4 threads per window ----
    int w  = tid >> 2;          // window 0..63
    int h  = tid & 3;           // quarter index
    int ti = w >> 3, tj = w & 7;

    float s0 = 0.f, s1 = 0.f, s2 = 0.f, s3;
    // s0: 16 c0 rows, 4 per thread
#pragma unroll
    for (int k = 0; k < 4; k++)
        s0 += c0[(ti + h * 4 + k) * 9 + tj];
    // s1: 8 c1 rows (stride 2), 2 per thread
#pragma unroll
    for (int k = 0; k < 2; k++)
        s1 += c1[(ti + 2 * (h * 2 + k)) * 9 + tj];
    // s2 and s4 share taps: row p=h of the 4x4 L2 grid (one LDS.64 per tap)
    float mx4 = -3.4e38f, mn4 = 3.4e38f;
#pragma unroll
    for (int q = 0; q < 4; q++) {
        float2 v = s[R2 + (ti + 4 * h) * P + tj + 4 * q];
        s2 += v.x - v.y;
        mx4 = fmaxf(mx4, v.x);
        mn4 = fminf(mn4, v.y);
    }
    // s3: thread h owns 32x32 box (h>>1, h&1) = max/min of 4 L2 entries
    {
        int b = R2 + (ti + 8 * (h >> 1)) * P + tj + 8 * (h & 1);
        float2 a0 = s[b],         a1 = s[b + 4];
        float2 a2 = s[b + 4 * P], a3 = s[b + 4 * P + 4];
        s3 = fmaxf(fmaxf(a0.x, a1.x), fmaxf(a2.x, a3.x))
           - fminf(fminf(a0.y, a1.y), fminf(a2.y, a3.y));
    }

    // Reduce across the 4-thread group (consecutive lanes)
#pragma unroll
    for (int off = 1; off <= 2; off <<= 1) {
        s0  += __shfl_xor_sync(0xFFFFFFFFu, s0, off);
        s1  += __shfl_xor_sync(0xFFFFFFFFu, s1, off);
        s2  += __shfl_xor_sync(0xFFFFFFFFu, s2, off);
        s3  += __shfl_xor_sync(0xFFFFFFFFu, s3, off);
        mx4 = fmaxf(mx4, __shfl_xor_sync(0xFFFFFFFFu, mx4, off));
        mn4 = fminf(mn4, __shfl_xor_sync(0xFFFFFFFFu, mn4, off));
    }

    int I = I0 + ti, J = J0 + tj;
    if (h == 0 && I < OH && J < OH) {
        float s4 = mx4 - mn4;
        float num = 2.0f * __log2f(s0) + 3.0f * __log2f(s1)
                  + 4.0f * __log2f(s2) + 5.0f * __log2f(s3)
                  + 6.0f * __log2f(s4);
        out[I * OH + J] = -num * (1.0f / 90.0f);
    }
}

// ---------------------------------------------------------------------------
extern "C" void kernel_launch(void* const* d_in, const int* in_sizes, int n_in,
                              void* d_out, int out_size) {
    const float* img = (const float*)d_in[0];
    float* out = (float*)d_out;
    dim3 grid(15, 15);          // ceil(113/8) per dim = 225 CTAs
    k_fused<<<grid, 256>>>(img, out);
}